// round 9
// baseline (speedup 1.0000x reference)
#include <cuda_runtime.h>

// ---------------------------------------------------------------------------
// GCN_84559316124289 — collapsed graph + f32x2 FMA, wave/occupancy-tuned.
//   P1 = pool(lrelu(conv1(x)+b1))
//   H2 = pool(lrelu(12*conv2w(P1) + 4*b2))
//   H3 = pool(lrelu(conv3(H2)+b3));  out[b] = wc . mean(H3) + bc
//
// k1: grid(32,4) = 128 blocks (one full wave), 8 couts per block (2 passes).
// k2: grid(32,4), 512 thr, 4 warps/SMSP, 4-cout subs, broadcast LDS.128 weights.
// k3: grid(32,4), 512 thr, 16 subs x 2 couts, broadcast LDS.64 weights.
// Epilogues store pooled col-pairs as coalesced float2.
// ---------------------------------------------------------------------------

typedef unsigned long long ull;

__device__ __forceinline__ ull dup2(float x) {
    ull r; asm("mov.b64 %0, {%1, %1};" : "=l"(r) : "f"(x)); return r;
}
__device__ __forceinline__ void ffma2(ull& d, ull a, ull b) {
    asm("fma.rn.f32x2 %0, %1, %2, %0;" : "+l"(d) : "l"(a), "l"(b));
}
__device__ __forceinline__ void unpk(float& lo, float& hi, ull v) {
    asm("mov.b64 {%0, %1}, %2;" : "=f"(lo), "=f"(hi) : "l"(v));
}

#define LRELU(t) ((t) > 0.f ? (t) : 0.2f * (t))

__device__ float g_P1[32 * 32 * 32 * 32];   // [B, 32, 32, 32]
__device__ float g_H2[32 * 64 * 16 * 16];   // [B, 64, 16, 16]

// Load 4x6 patch and duplicate each value into an f32x2 register.
#define LOAD_PATCH(IB, RS)                                                     \
    ull pd[4][6];                                                              \
    _Pragma("unroll")                                                          \
    for (int r = 0; r < 4; r++) {                                              \
        float4 a4 = *(const float4*)((IB) + r * (RS));                         \
        float2 b2v = *(const float2*)((IB) + r * (RS) + 4);                    \
        pd[r][0] = dup2(a4.x);  pd[r][1] = dup2(a4.y);                         \
        pd[r][2] = dup2(a4.z);  pd[r][3] = dup2(a4.w);                         \
        pd[r][4] = dup2(b2v.x); pd[r][5] = dup2(b2v.y);                        \
    }

// Two cout-pairs (4 couts): 9 broadcast LDS.128, 16 FFMA2 / k.
#define CONV_CI_2P(IB, WP, RS, WS)                                             \
    {                                                                          \
        LOAD_PATCH(IB, RS)                                                     \
        _Pragma("unroll")                                                      \
        for (int k = 0; k < 9; k++) {                                          \
            ulonglong2 w = *(const ulonglong2*)((WP) + k * (WS));              \
            int ky = k / 3, kx = k - ky * 3;                                   \
            _Pragma("unroll")                                                  \
            for (int dy = 0; dy < 2; dy++)                                     \
                _Pragma("unroll")                                              \
                for (int dx = 0; dx < 4; dx++) {                               \
                    ull pv = pd[dy + ky][dx + kx];                             \
                    int q = dy * 4 + dx;                                       \
                    ffma2(acc[0][q], pv, w.x);                                 \
                    ffma2(acc[1][q], pv, w.y);                                 \
                }                                                              \
        }                                                                      \
    }

// One cout-pair (2 couts): 9 broadcast LDS.64, 8 FFMA2 / k.
#define CONV_CI_1P(IB, WP, RS, WS)                                             \
    {                                                                          \
        LOAD_PATCH(IB, RS)                                                     \
        _Pragma("unroll")                                                      \
        for (int k = 0; k < 9; k++) {                                          \
            ull w = *(const ull*)((WP) + k * (WS));                            \
            int ky = k / 3, kx = k - ky * 3;                                   \
            _Pragma("unroll")                                                  \
            for (int dy = 0; dy < 2; dy++)                                     \
                _Pragma("unroll")                                              \
                for (int dx = 0; dx < 4; dx++)                                 \
                    ffma2(acc[dy * 4 + dx], pd[dy + ky][dx + kx], w);          \
        }                                                                      \
    }

// ---------------------------------------------------------------------------
// Kernel 1: conv1 (4->32) + lrelu + pool.  grid(32,4) block 512.
// 8 couts per block, 2 passes of 4 couts; 512 1x2-pooled tiles.
// s_in: 4ch x 66 x stride 68.  s_w: [ci*9+k]*8 + co(0..7).
// ---------------------------------------------------------------------------
__global__ void __launch_bounds__(512, 1)
k1_conv(const float* __restrict__ x,
        const float* __restrict__ w1,
        const float* __restrict__ b1,
        const float* __restrict__ bc,
        float* __restrict__ out) {
    extern __shared__ float sm[];
    float* s_in = sm;                  // 4*4488 = 17952
    float* s_w  = sm + 17952;          // 36*8 = 288

    const int b  = blockIdx.x;
    const int cg = blockIdx.y;         // couts [cg*8, cg*8+8)
    const int tid = threadIdx.x;

    if (cg == 0 && tid == 0) out[b] = bc[0];

    const float* xb = x + b * 16384;
    for (int j = tid; j < 4096; j += 512) {
        float4 v = *(const float4*)(xb + j * 4);
        int c = j >> 10, r = (j >> 4) & 63, x0 = (j & 15) * 4;
        float* d = s_in + c * 4488 + (r + 1) * 68 + x0 + 1;
        d[0] = v.x; d[1] = v.y; d[2] = v.z; d[3] = v.w;
    }
    for (int i = tid; i < 4 * 264; i += 512) {
        int c = i / 264, t = i - c * 264;
        int row, col;
        if (t < 136) { row = (t >= 68) ? 65 : 0; col = t % 68; }
        else { int tt = t - 136; row = 1 + (tt >> 1); col = (tt & 1) ? 65 : 0; }
        s_in[c * 4488 + row * 68 + col] = 0.f;
    }
    if (tid < 288) {
        int co = tid / 36, r = tid - co * 36;
        s_w[r * 8 + co] = w1[cg * 288 + tid];
    }
    __syncthreads();

    const int gh = tid >> 4, gw = tid & 15;

    #pragma unroll 1
    for (int sp = 0; sp < 2; sp++) {
        ull acc[2][8];
        #pragma unroll
        for (int j = 0; j < 2; j++)
            #pragma unroll
            for (int q = 0; q < 8; q++) acc[j][q] = 0ull;

        #pragma unroll
        for (int ci = 0; ci < 4; ci++) {
            const float* ib = s_in + ci * 4488 + (2 * gh) * 68 + 4 * gw;
            const float* wp = s_w + ci * 72 + sp * 4;
            CONV_CI_2P(ib, wp, 68, 8)
        }

        #pragma unroll
        for (int j = 0; j < 2; j++) {
            float v0[8], v1[8];
            #pragma unroll
            for (int q = 0; q < 8; q++) unpk(v0[q], v1[q], acc[j][q]);
            int co0 = cg * 8 + sp * 4 + 2 * j;
            float bb0 = b1[co0], bb1 = b1[co0 + 1];
            float m0[2], m1[2];
            #pragma unroll
            for (int c2 = 0; c2 < 2; c2++) {
                float a0 = -1e30f, a1 = -1e30f;
                #pragma unroll
                for (int dy = 0; dy < 2; dy++)
                    #pragma unroll
                    for (int dx = 0; dx < 2; dx++) {
                        int q = dy * 4 + 2 * c2 + dx;
                        float t0 = v0[q] + bb0; t0 = LRELU(t0); a0 = fmaxf(a0, t0);
                        float t1 = v1[q] + bb1; t1 = LRELU(t1); a1 = fmaxf(a1, t1);
                    }
                m0[c2] = a0; m1[c2] = a1;
            }
            *(float2*)(g_P1 + (b * 32 + co0) * 1024 + gh * 32 + 2 * gw) =
                make_float2(m0[0], m0[1]);
            *(float2*)(g_P1 + (b * 32 + co0 + 1) * 1024 + gh * 32 + 2 * gw) =
                make_float2(m1[0], m1[1]);
        }
    }
}

// ---------------------------------------------------------------------------
// Kernel 2: 12*conv2w (32->64) + 4*b2, lrelu, pool.  grid(32,4) block 512.
// 4 subs (4 couts) x 128 tiles; warp-uniform sub.
// s_in: 32ch x 34 x stride 36.  s_w: [ci*9+k]*20 + co(0..15).
// ---------------------------------------------------------------------------
__global__ void __launch_bounds__(512, 1)
k2_conv(const float* __restrict__ w2,
        const float* __restrict__ b2) {
    extern __shared__ float sm[];
    float* s_in = sm;                  // 32*1224 = 39168
    float* s_w  = sm + 39168;          // 288*20 = 5760

    const int b  = blockIdx.x;
    const int cg = blockIdx.y;
    const int tid = threadIdx.x;

    const float* pb = g_P1 + b * 32768;
    for (int j = tid; j < 8192; j += 512) {
        float4 v = *(const float4*)(pb + j * 4);
        int c = j >> 8, r = (j >> 3) & 31, x0 = (j & 7) * 4;
        float* d = s_in + c * 1224 + (r + 1) * 36 + x0 + 1;
        d[0] = v.x; d[1] = v.y; d[2] = v.z; d[3] = v.w;
    }
    for (int i = tid; i < 32 * 136; i += 512) {
        int c = i / 136, t = i - c * 136;
        int row, col;
        if (t < 72) { row = (t >= 36) ? 33 : 0; col = t % 36; }
        else { int tt = t - 72; row = 1 + (tt >> 1); col = (tt & 1) ? 33 : 0; }
        s_in[c * 1224 + row * 36 + col] = 0.f;
    }
    for (int i = tid * 4; i < 4608; i += 2048) {
        float4 wv = *(const float4*)(w2 + cg * 4608 + i);
        int co = i / 288, r = i - co * 288;
        s_w[(r + 0) * 20 + co] = wv.x;
        s_w[(r + 1) * 20 + co] = wv.y;
        s_w[(r + 2) * 20 + co] = wv.z;
        s_w[(r + 3) * 20 + co] = wv.w;
    }
    __syncthreads();

    const int sub = tid >> 7;
    const int pxg = tid & 127;
    const int gh = pxg >> 3, gw = pxg & 7;

    ull acc[2][8];
    #pragma unroll
    for (int j = 0; j < 2; j++)
        #pragma unroll
        for (int q = 0; q < 8; q++) acc[j][q] = 0ull;

    for (int ci = 0; ci < 32; ci++) {
        const float* ib = s_in + ci * 1224 + (2 * gh) * 36 + 4 * gw;
        const float* wp = s_w + ci * 180 + sub * 4;
        CONV_CI_2P(ib, wp, 36, 20)
    }

    #pragma unroll
    for (int j = 0; j < 2; j++) {
        float v0[8], v1[8];
        #pragma unroll
        for (int q = 0; q < 8; q++) unpk(v0[q], v1[q], acc[j][q]);
        int co0 = cg * 16 + sub * 4 + 2 * j;
        float bb0 = 4.f * b2[co0], bb1 = 4.f * b2[co0 + 1];
        float m0[2], m1[2];
        #pragma unroll
        for (int c2 = 0; c2 < 2; c2++) {
            float a0 = -1e30f, a1 = -1e30f;
            #pragma unroll
            for (int dy = 0; dy < 2; dy++)
                #pragma unroll
                for (int dx = 0; dx < 2; dx++) {
                    int q = dy * 4 + 2 * c2 + dx;
                    float t0 = fmaf(12.f, v0[q], bb0); t0 = LRELU(t0); a0 = fmaxf(a0, t0);
                    float t1 = fmaf(12.f, v1[q], bb1); t1 = LRELU(t1); a1 = fmaxf(a1, t1);
                }
            m0[c2] = a0; m1[c2] = a1;
        }
        *(float2*)(g_H2 + (b * 64 + co0) * 256 + gh * 16 + 2 * gw) =
            make_float2(m0[0], m0[1]);
        *(float2*)(g_H2 + (b * 64 + co0 + 1) * 256 + gh * 16 + 2 * gw) =
            make_float2(m1[0], m1[1]);
    }
}

// ---------------------------------------------------------------------------
// Kernel 3: conv3 (64->128) + lrelu + pool + mean + dot(wc).  grid(32,4), 512.
// 16 subs (2 couts) x 32 tiles; warp-uniform sub; broadcast LDS.64 weights.
// s_in: 64ch x 18 x stride 20.  s_w: [ci*9+k]*36 + co(0..31).
// ---------------------------------------------------------------------------
__global__ void __launch_bounds__(512, 1)
k3_conv(const float* __restrict__ w3,
        const float* __restrict__ b3,
        const float* __restrict__ wc,
        float* __restrict__ out) {
    extern __shared__ float sm[];
    float* s_in  = sm;                 // 64*360 = 23040
    float* s_w   = sm + 23040;         // 576*36 = 20736
    float* s_red = s_w + 20736;        // 32*65 = 2080

    const int b  = blockIdx.x;
    const int cg = blockIdx.y;
    const int tid = threadIdx.x;

    const float* hb = g_H2 + b * 16384;
    for (int j = tid; j < 4096; j += 512) {
        float4 v = *(const float4*)(hb + j * 4);
        int c = j >> 6, r = (j >> 2) & 15, x0 = (j & 3) * 4;
        float* d = s_in + c * 360 + (r + 1) * 20 + x0 + 1;
        d[0] = v.x; d[1] = v.y; d[2] = v.z; d[3] = v.w;
    }
    for (int i = tid; i < 64 * 72; i += 512) {
        int c = i / 72, t = i - c * 72;
        int row, col;
        if (t < 40) { row = (t >= 20) ? 17 : 0; col = t % 20; }
        else { int tt = t - 40; row = 1 + (tt >> 1); col = (tt & 1) ? 17 : 0; }
        s_in[c * 360 + row * 20 + col] = 0.f;
    }
    for (int i = tid * 4; i < 18432; i += 2048) {
        float4 wv = *(const float4*)(w3 + cg * 18432 + i);
        int co = i / 576, r = i - co * 576;
        s_w[(r + 0) * 36 + co] = wv.x;
        s_w[(r + 1) * 36 + co] = wv.y;
        s_w[(r + 2) * 36 + co] = wv.z;
        s_w[(r + 3) * 36 + co] = wv.w;
    }
    __syncthreads();

    const int sub = tid >> 5;          // 0..15 -> couts sub*2, sub*2+1
    const int pxg = tid & 31;
    const int gh = pxg >> 2, gw = pxg & 3;

    ull acc[8];
    #pragma unroll
    for (int q = 0; q < 8; q++) acc[q] = 0ull;

    for (int ci = 0; ci < 64; ci++) {
        const float* ib = s_in + ci * 360 + (2 * gh) * 20 + 4 * gw;
        const float* wp = s_w + ci * 324 + sub * 2;
        CONV_CI_1P(ib, wp, 20, 36)
    }

    {
        float v0[8], v1[8];
        #pragma unroll
        for (int q = 0; q < 8; q++) unpk(v0[q], v1[q], acc[q]);
        int lco0 = sub * 2;
        float bb0 = b3[cg * 32 + lco0], bb1 = b3[cg * 32 + lco0 + 1];
        #pragma unroll
        for (int c2 = 0; c2 < 2; c2++) {
            float a0 = -1e30f, a1 = -1e30f;
            #pragma unroll
            for (int dy = 0; dy < 2; dy++)
                #pragma unroll
                for (int dx = 0; dx < 2; dx++) {
                    int q = dy * 4 + 2 * c2 + dx;
                    float t0 = v0[q] + bb0; t0 = LRELU(t0); a0 = fmaxf(a0, t0);
                    float t1 = v1[q] + bb1; t1 = LRELU(t1); a1 = fmaxf(a1, t1);
                }
            int ppx = gh * 8 + 2 * gw + c2;
            s_red[lco0 * 65 + ppx] = a0;
            s_red[(lco0 + 1) * 65 + ppx] = a1;
        }
    }
    __syncthreads();

    if (tid < 32) {
        float s = 0.f;
        #pragma unroll 8
        for (int p2 = 0; p2 < 64; p2++) s += s_red[tid * 65 + p2];
        float part = wc[cg * 32 + tid] * s * (1.0f / 64.0f);
        #pragma unroll
        for (int off = 16; off; off >>= 1)
            part += __shfl_down_sync(0xffffffffu, part, off);
        if (tid == 0) atomicAdd(&out[b], part);
    }
}

extern "C" void kernel_launch(void* const* d_in, const int* in_sizes, int n_in,
                              void* d_out, int out_size) {
    const float* x  = (const float*)d_in[0];
    const float* w1 = (const float*)d_in[1];
    const float* b1 = (const float*)d_in[2];
    const float* w2 = (const float*)d_in[3];
    const float* b2 = (const float*)d_in[4];
    const float* w3 = (const float*)d_in[5];
    const float* b3 = (const float*)d_in[6];
    const float* wc = (const float*)d_in[7];
    const float* bc = (const float*)d_in[8];
    float* out = (float*)d_out;

    const size_t sm1 = (17952 + 288) * sizeof(float);           //  73 KB
    const size_t sm2 = (39168 + 5760) * sizeof(float);          // 180 KB
    const size_t sm3 = (23040 + 20736 + 2080) * sizeof(float);  // 183 KB

    cudaFuncSetAttribute(k1_conv, cudaFuncAttributeMaxDynamicSharedMemorySize, (int)sm1);
    cudaFuncSetAttribute(k2_conv, cudaFuncAttributeMaxDynamicSharedMemorySize, (int)sm2);
    cudaFuncSetAttribute(k3_conv, cudaFuncAttributeMaxDynamicSharedMemorySize, (int)sm3);

    k1_conv<<<dim3(32, 4), 512, sm1>>>(x, w1, b1, bc, out);
    k2_conv<<<dim3(32, 4), 512, sm2>>>(w2, b2);
    k3_conv<<<dim3(32, 4), 512, sm3>>>(w3, b3, wc, out);
}

// round 10
// speedup vs baseline: 1.0059x; 1.0059x over previous
#include <cuda_runtime.h>

// ---------------------------------------------------------------------------
// GCN_84559316124289 — collapsed graph + f32x2 FMA, wave/occupancy-tuned.
//   P1 = pool(lrelu(conv1(x)+b1))
//   H2 = pool(lrelu(12*conv2w(P1) + 4*b2))
//   H3 = pool(lrelu(conv3(H2)+b3));  out[b] = wc . mean(H3) + bc
//
// k1: grid(32,4) = 128 blocks (one full wave), 8 couts per block (2 passes).
// k2: grid(32,4), 512 thr, 4 warps/SMSP, 4-cout subs, broadcast LDS.128 weights.
// k3: grid(32,4), 512 thr, 16 subs x 2 couts, broadcast LDS.64 weights.
// Epilogues store pooled col-pairs as coalesced float2.
// ---------------------------------------------------------------------------

typedef unsigned long long ull;

__device__ __forceinline__ ull dup2(float x) {
    ull r; asm("mov.b64 %0, {%1, %1};" : "=l"(r) : "f"(x)); return r;
}
__device__ __forceinline__ void ffma2(ull& d, ull a, ull b) {
    asm("fma.rn.f32x2 %0, %1, %2, %0;" : "+l"(d) : "l"(a), "l"(b));
}
__device__ __forceinline__ void unpk(float& lo, float& hi, ull v) {
    asm("mov.b64 {%0, %1}, %2;" : "=f"(lo), "=f"(hi) : "l"(v));
}

#define LRELU(t) ((t) > 0.f ? (t) : 0.2f * (t))

__device__ float g_P1[32 * 32 * 32 * 32];   // [B, 32, 32, 32]
__device__ float g_H2[32 * 64 * 16 * 16];   // [B, 64, 16, 16]

// Load 4x6 patch and duplicate each value into an f32x2 register.
#define LOAD_PATCH(IB, RS)                                                     \
    ull pd[4][6];                                                              \
    _Pragma("unroll")                                                          \
    for (int r = 0; r < 4; r++) {                                              \
        float4 a4 = *(const float4*)((IB) + r * (RS));                         \
        float2 b2v = *(const float2*)((IB) + r * (RS) + 4);                    \
        pd[r][0] = dup2(a4.x);  pd[r][1] = dup2(a4.y);                         \
        pd[r][2] = dup2(a4.z);  pd[r][3] = dup2(a4.w);                         \
        pd[r][4] = dup2(b2v.x); pd[r][5] = dup2(b2v.y);                        \
    }

// Two cout-pairs (4 couts): 9 broadcast LDS.128, 16 FFMA2 / k.
#define CONV_CI_2P(IB, WP, RS, WS)                                             \
    {                                                                          \
        LOAD_PATCH(IB, RS)                                                     \
        _Pragma("unroll")                                                      \
        for (int k = 0; k < 9; k++) {                                          \
            ulonglong2 w = *(const ulonglong2*)((WP) + k * (WS));              \
            int ky = k / 3, kx = k - ky * 3;                                   \
            _Pragma("unroll")                                                  \
            for (int dy = 0; dy < 2; dy++)                                     \
                _Pragma("unroll")                                              \
                for (int dx = 0; dx < 4; dx++) {                               \
                    ull pv = pd[dy + ky][dx + kx];                             \
                    int q = dy * 4 + dx;                                       \
                    ffma2(acc[0][q], pv, w.x);                                 \
                    ffma2(acc[1][q], pv, w.y);                                 \
                }                                                              \
        }                                                                      \
    }

// One cout-pair (2 couts): 9 broadcast LDS.64, 8 FFMA2 / k.
#define CONV_CI_1P(IB, WP, RS, WS)                                             \
    {                                                                          \
        LOAD_PATCH(IB, RS)                                                     \
        _Pragma("unroll")                                                      \
        for (int k = 0; k < 9; k++) {                                          \
            ull w = *(const ull*)((WP) + k * (WS));                            \
            int ky = k / 3, kx = k - ky * 3;                                   \
            _Pragma("unroll")                                                  \
            for (int dy = 0; dy < 2; dy++)                                     \
                _Pragma("unroll")                                              \
                for (int dx = 0; dx < 4; dx++)                                 \
                    ffma2(acc[dy * 4 + dx], pd[dy + ky][dx + kx], w);          \
        }                                                                      \
    }

// ---------------------------------------------------------------------------
// Kernel 1: conv1 (4->32) + lrelu + pool.  grid(32,4) block 512.
// 8 couts per block, 2 passes of 4 couts; 512 1x2-pooled tiles.
// s_in: 4ch x 66 x stride 68.  s_w: [ci*9+k]*8 + co(0..7).
// ---------------------------------------------------------------------------
__global__ void __launch_bounds__(512, 1)
k1_conv(const float* __restrict__ x,
        const float* __restrict__ w1,
        const float* __restrict__ b1,
        const float* __restrict__ bc,
        float* __restrict__ out) {
    extern __shared__ float sm[];
    float* s_in = sm;                  // 4*4488 = 17952
    float* s_w  = sm + 17952;          // 36*8 = 288

    const int b  = blockIdx.x;
    const int cg = blockIdx.y;         // couts [cg*8, cg*8+8)
    const int tid = threadIdx.x;

    if (cg == 0 && tid == 0) out[b] = bc[0];

    const float* xb = x + b * 16384;
    for (int j = tid; j < 4096; j += 512) {
        float4 v = *(const float4*)(xb + j * 4);
        int c = j >> 10, r = (j >> 4) & 63, x0 = (j & 15) * 4;
        float* d = s_in + c * 4488 + (r + 1) * 68 + x0 + 1;
        d[0] = v.x; d[1] = v.y; d[2] = v.z; d[3] = v.w;
    }
    for (int i = tid; i < 4 * 264; i += 512) {
        int c = i / 264, t = i - c * 264;
        int row, col;
        if (t < 136) { row = (t >= 68) ? 65 : 0; col = t % 68; }
        else { int tt = t - 136; row = 1 + (tt >> 1); col = (tt & 1) ? 65 : 0; }
        s_in[c * 4488 + row * 68 + col] = 0.f;
    }
    if (tid < 288) {
        int co = tid / 36, r = tid - co * 36;
        s_w[r * 8 + co] = w1[cg * 288 + tid];
    }
    __syncthreads();

    const int gh = tid >> 4, gw = tid & 15;

    #pragma unroll 1
    for (int sp = 0; sp < 2; sp++) {
        ull acc[2][8];
        #pragma unroll
        for (int j = 0; j < 2; j++)
            #pragma unroll
            for (int q = 0; q < 8; q++) acc[j][q] = 0ull;

        #pragma unroll
        for (int ci = 0; ci < 4; ci++) {
            const float* ib = s_in + ci * 4488 + (2 * gh) * 68 + 4 * gw;
            const float* wp = s_w + ci * 72 + sp * 4;
            CONV_CI_2P(ib, wp, 68, 8)
        }

        #pragma unroll
        for (int j = 0; j < 2; j++) {
            float v0[8], v1[8];
            #pragma unroll
            for (int q = 0; q < 8; q++) unpk(v0[q], v1[q], acc[j][q]);
            int co0 = cg * 8 + sp * 4 + 2 * j;
            float bb0 = b1[co0], bb1 = b1[co0 + 1];
            float m0[2], m1[2];
            #pragma unroll
            for (int c2 = 0; c2 < 2; c2++) {
                float a0 = -1e30f, a1 = -1e30f;
                #pragma unroll
                for (int dy = 0; dy < 2; dy++)
                    #pragma unroll
                    for (int dx = 0; dx < 2; dx++) {
                        int q = dy * 4 + 2 * c2 + dx;
                        float t0 = v0[q] + bb0; t0 = LRELU(t0); a0 = fmaxf(a0, t0);
                        float t1 = v1[q] + bb1; t1 = LRELU(t1); a1 = fmaxf(a1, t1);
                    }
                m0[c2] = a0; m1[c2] = a1;
            }
            *(float2*)(g_P1 + (b * 32 + co0) * 1024 + gh * 32 + 2 * gw) =
                make_float2(m0[0], m0[1]);
            *(float2*)(g_P1 + (b * 32 + co0 + 1) * 1024 + gh * 32 + 2 * gw) =
                make_float2(m1[0], m1[1]);
        }
    }
}

// ---------------------------------------------------------------------------
// Kernel 2: 12*conv2w (32->64) + 4*b2, lrelu, pool.  grid(32,4) block 512.
// 4 subs (4 couts) x 128 tiles; warp-uniform sub.
// s_in: 32ch x 34 x stride 36.  s_w: [ci*9+k]*20 + co(0..15).
// ---------------------------------------------------------------------------
__global__ void __launch_bounds__(512, 1)
k2_conv(const float* __restrict__ w2,
        const float* __restrict__ b2) {
    extern __shared__ float sm[];
    float* s_in = sm;                  // 32*1224 = 39168
    float* s_w  = sm + 39168;          // 288*20 = 5760

    const int b  = blockIdx.x;
    const int cg = blockIdx.y;
    const int tid = threadIdx.x;

    const float* pb = g_P1 + b * 32768;
    for (int j = tid; j < 8192; j += 512) {
        float4 v = *(const float4*)(pb + j * 4);
        int c = j >> 8, r = (j >> 3) & 31, x0 = (j & 7) * 4;
        float* d = s_in + c * 1224 + (r + 1) * 36 + x0 + 1;
        d[0] = v.x; d[1] = v.y; d[2] = v.z; d[3] = v.w;
    }
    for (int i = tid; i < 32 * 136; i += 512) {
        int c = i / 136, t = i - c * 136;
        int row, col;
        if (t < 72) { row = (t >= 36) ? 33 : 0; col = t % 36; }
        else { int tt = t - 72; row = 1 + (tt >> 1); col = (tt & 1) ? 33 : 0; }
        s_in[c * 1224 + row * 36 + col] = 0.f;
    }
    for (int i = tid * 4; i < 4608; i += 2048) {
        float4 wv = *(const float4*)(w2 + cg * 4608 + i);
        int co = i / 288, r = i - co * 288;
        s_w[(r + 0) * 20 + co] = wv.x;
        s_w[(r + 1) * 20 + co] = wv.y;
        s_w[(r + 2) * 20 + co] = wv.z;
        s_w[(r + 3) * 20 + co] = wv.w;
    }
    __syncthreads();

    const int sub = tid >> 7;
    const int pxg = tid & 127;
    const int gh = pxg >> 3, gw = pxg & 7;

    ull acc[2][8];
    #pragma unroll
    for (int j = 0; j < 2; j++)
        #pragma unroll
        for (int q = 0; q < 8; q++) acc[j][q] = 0ull;

    for (int ci = 0; ci < 32; ci++) {
        const float* ib = s_in + ci * 1224 + (2 * gh) * 36 + 4 * gw;
        const float* wp = s_w + ci * 180 + sub * 4;
        CONV_CI_2P(ib, wp, 36, 20)
    }

    #pragma unroll
    for (int j = 0; j < 2; j++) {
        float v0[8], v1[8];
        #pragma unroll
        for (int q = 0; q < 8; q++) unpk(v0[q], v1[q], acc[j][q]);
        int co0 = cg * 16 + sub * 4 + 2 * j;
        float bb0 = 4.f * b2[co0], bb1 = 4.f * b2[co0 + 1];
        float m0[2], m1[2];
        #pragma unroll
        for (int c2 = 0; c2 < 2; c2++) {
            float a0 = -1e30f, a1 = -1e30f;
            #pragma unroll
            for (int dy = 0; dy < 2; dy++)
                #pragma unroll
                for (int dx = 0; dx < 2; dx++) {
                    int q = dy * 4 + 2 * c2 + dx;
                    float t0 = fmaf(12.f, v0[q], bb0); t0 = LRELU(t0); a0 = fmaxf(a0, t0);
                    float t1 = fmaf(12.f, v1[q], bb1); t1 = LRELU(t1); a1 = fmaxf(a1, t1);
                }
            m0[c2] = a0; m1[c2] = a1;
        }
        *(float2*)(g_H2 + (b * 64 + co0) * 256 + gh * 16 + 2 * gw) =
            make_float2(m0[0], m0[1]);
        *(float2*)(g_H2 + (b * 64 + co0 + 1) * 256 + gh * 16 + 2 * gw) =
            make_float2(m1[0], m1[1]);
    }
}

// ---------------------------------------------------------------------------
// Kernel 3: conv3 (64->128) + lrelu + pool + mean + dot(wc).  grid(32,4), 512.
// 16 subs (2 couts) x 32 tiles; warp-uniform sub; broadcast LDS.64 weights.
// s_in: 64ch x 18 x stride 20.  s_w: [ci*9+k]*36 + co(0..31).
// ---------------------------------------------------------------------------
__global__ void __launch_bounds__(512, 1)
k3_conv(const float* __restrict__ w3,
        const float* __restrict__ b3,
        const float* __restrict__ wc,
        float* __restrict__ out) {
    extern __shared__ float sm[];
    float* s_in  = sm;                 // 64*360 = 23040
    float* s_w   = sm + 23040;         // 576*36 = 20736
    float* s_red = s_w + 20736;        // 32*65 = 2080

    const int b  = blockIdx.x;
    const int cg = blockIdx.y;
    const int tid = threadIdx.x;

    const float* hb = g_H2 + b * 16384;
    for (int j = tid; j < 4096; j += 512) {
        float4 v = *(const float4*)(hb + j * 4);
        int c = j >> 6, r = (j >> 2) & 15, x0 = (j & 3) * 4;
        float* d = s_in + c * 360 + (r + 1) * 20 + x0 + 1;
        d[0] = v.x; d[1] = v.y; d[2] = v.z; d[3] = v.w;
    }
    for (int i = tid; i < 64 * 72; i += 512) {
        int c = i / 72, t = i - c * 72;
        int row, col;
        if (t < 40) { row = (t >= 20) ? 17 : 0; col = t % 20; }
        else { int tt = t - 40; row = 1 + (tt >> 1); col = (tt & 1) ? 17 : 0; }
        s_in[c * 360 + row * 20 + col] = 0.f;
    }
    for (int i = tid * 4; i < 18432; i += 2048) {
        float4 wv = *(const float4*)(w3 + cg * 18432 + i);
        int co = i / 576, r = i - co * 576;
        s_w[(r + 0) * 36 + co] = wv.x;
        s_w[(r + 1) * 36 + co] = wv.y;
        s_w[(r + 2) * 36 + co] = wv.z;
        s_w[(r + 3) * 36 + co] = wv.w;
    }
    __syncthreads();

    const int sub = tid >> 5;          // 0..15 -> couts sub*2, sub*2+1
    const int pxg = tid & 31;
    const int gh = pxg >> 2, gw = pxg & 3;

    ull acc[8];
    #pragma unroll
    for (int q = 0; q < 8; q++) acc[q] = 0ull;

    for (int ci = 0; ci < 64; ci++) {
        const float* ib = s_in + ci * 360 + (2 * gh) * 20 + 4 * gw;
        const float* wp = s_w + ci * 324 + sub * 2;
        CONV_CI_1P(ib, wp, 20, 36)
    }

    {
        float v0[8], v1[8];
        #pragma unroll
        for (int q = 0; q < 8; q++) unpk(v0[q], v1[q], acc[q]);
        int lco0 = sub * 2;
        float bb0 = b3[cg * 32 + lco0], bb1 = b3[cg * 32 + lco0 + 1];
        #pragma unroll
        for (int c2 = 0; c2 < 2; c2++) {
            float a0 = -1e30f, a1 = -1e30f;
            #pragma unroll
            for (int dy = 0; dy < 2; dy++)
                #pragma unroll
                for (int dx = 0; dx < 2; dx++) {
                    int q = dy * 4 + 2 * c2 + dx;
                    float t0 = v0[q] + bb0; t0 = LRELU(t0); a0 = fmaxf(a0, t0);
                    float t1 = v1[q] + bb1; t1 = LRELU(t1); a1 = fmaxf(a1, t1);
                }
            int ppx = gh * 8 + 2 * gw + c2;
            s_red[lco0 * 65 + ppx] = a0;
            s_red[(lco0 + 1) * 65 + ppx] = a1;
        }
    }
    __syncthreads();

    if (tid < 32) {
        float s = 0.f;
        #pragma unroll 8
        for (int p2 = 0; p2 < 64; p2++) s += s_red[tid * 65 + p2];
        float part = wc[cg * 32 + tid] * s * (1.0f / 64.0f);
        #pragma unroll
        for (int off = 16; off; off >>= 1)
            part += __shfl_down_sync(0xffffffffu, part, off);
        if (tid == 0) atomicAdd(&out[b], part);
    }
}

extern "C" void kernel_launch(void* const* d_in, const int* in_sizes, int n_in,
                              void* d_out, int out_size) {
    const float* x  = (const float*)d_in[0];
    const float* w1 = (const float*)d_in[1];
    const float* b1 = (const float*)d_in[2];
    const float* w2 = (const float*)d_in[3];
    const float* b2 = (const float*)d_in[4];
    const float* w3 = (const float*)d_in[5];
    const float* b3 = (const float*)d_in[6];
    const float* wc = (const float*)d_in[7];
    const float* bc = (const float*)d_in[8];
    float* out = (float*)d_out;

    const size_t sm1 = (17952 + 288) * sizeof(float);           //  73 KB
    const size_t sm2 = (39168 + 5760) * sizeof(float);          // 180 KB
    const size_t sm3 = (23040 + 20736 + 2080) * sizeof(float);  // 183 KB

    cudaFuncSetAttribute(k1_conv, cudaFuncAttributeMaxDynamicSharedMemorySize, (int)sm1);
    cudaFuncSetAttribute(k2_conv, cudaFuncAttributeMaxDynamicSharedMemorySize, (int)sm2);
    cudaFuncSetAttribute(k3_conv, cudaFuncAttributeMaxDynamicSharedMemorySize, (int)sm3);

    k1_conv<<<dim3(32, 4), 512, sm1>>>(x, w1, b1, bc, out);
    k2_conv<<<dim3(32, 4), 512, sm2>>>(w2, b2);
    k3_conv<<<dim3(32, 4), 512, sm3>>>(w3, b3, wc, out);
}